// round 1
// baseline (speedup 1.0000x reference)
#include <cuda_runtime.h>
#include <cstdint>

#define LNUM 3
#define BSZ  32
#define SEQ  512
#define DIM  512
#define WPAD 3
#define MTOT (BSZ * SEQ)          // 16384 tokens
#define DD   (DIM * DIM)
#define EPSV 1e-6f

// ---------------- scratch (device globals; no allocation) ----------------
__device__ float g_x[2][MTOT * DIM];   // carried state per direction
__device__ float g_y[2][MTOT * DIM];   // pre-LN conv output (residual source)
__device__ float g_z[2][MTOT * DIM];   // LN output (GEMM1 input)
__device__ float g_h[2][MTOT * DIM];   // FFN hidden (GEMM2 input)

// ---------------- helpers ----------------
__device__ __forceinline__ float warpSum(float v) {
#pragma unroll
    for (int o = 16; o > 0; o >>= 1) v += __shfl_xor_sync(0xffffffffu, v, o);
    return v;
}

__device__ __forceinline__ void split_tf32(float x, uint32_t& hi, uint32_t& lo) {
    uint32_t h;
    asm("cvt.rna.tf32.f32 %0, %1;" : "=r"(h) : "f"(x));
    float rest = x - __uint_as_float(h);
    uint32_t l;
    asm("cvt.rna.tf32.f32 %0, %1;" : "=r"(l) : "f"(rest));
    hi = h; lo = l;
}

__device__ __forceinline__ void mma_tf32(float* c, const uint32_t* a, const uint32_t* b) {
    asm volatile(
        "mma.sync.aligned.m16n8k8.row.col.f32.tf32.tf32.f32 "
        "{%0,%1,%2,%3}, {%4,%5,%6,%7}, {%8,%9}, {%0,%1,%2,%3};"
        : "+f"(c[0]), "+f"(c[1]), "+f"(c[2]), "+f"(c[3])
        : "r"(a[0]), "r"(a[1]), "r"(a[2]), "r"(a[3]), "r"(b[0]), "r"(b[1]));
}

// ---------------- kernel 1: window conv + LayerNorm (both dirs) ----------------
// grid: (MTOT, 2), block: 256. Each thread handles 2 of 512 dims.
__global__ void conv_ln_kernel(const float* __restrict__ ext_x, int layer,
                               const float* __restrict__ fpad,  // [W, D] (layer slice)
                               const float* __restrict__ bpad,  // [W, D]
                               const float* __restrict__ fwt,   // [4]
                               const float* __restrict__ bwt,   // [4]
                               const float* __restrict__ fg, const float* __restrict__ fb,
                               const float* __restrict__ bg, const float* __restrict__ bb) {
    const int dir   = blockIdx.y;
    const int token = blockIdx.x;
    const int b = token >> 9;
    const int s = token & 511;
    const float* src   = (layer == 0) ? ext_x : g_x[dir];
    const float* wt    = dir ? bwt : fwt;
    const float* gamma = dir ? bg : fg;
    const float* beta  = dir ? bb : fb;
    const int off = dir ? WPAD : 0;
    const int tid = threadIdx.x;

    float w[4];
#pragma unroll
    for (int k = 0; k < 4; k++) w[k] = wt[k];

    float yl[2];
#pragma unroll
    for (int e = 0; e < 2; e++) {
        const int d = tid + e * 256;
        float acc = 0.f;
#pragma unroll
        for (int k = 0; k < 4; k++) {
            const int j = s + off + k;   // index into padded sequence [0, S+2W)
            float v;
            if (j < WPAD)             v = fpad[j * DIM + d];
            else if (j < WPAD + SEQ)  v = src[((size_t)b * SEQ + (j - WPAD)) * DIM + d];
            else                      v = bpad[(j - WPAD - SEQ) * DIM + d];
            acc += w[k] * v;
        }
        yl[e] = acc;
    }

    __shared__ float sh[8];
    __shared__ float stat[2];
    const int lane = tid & 31, wid = tid >> 5;

    float v = warpSum(yl[0] + yl[1]);
    if (lane == 0) sh[wid] = v;
    __syncthreads();
    if (tid == 0) {
        float t = 0.f;
#pragma unroll
        for (int i = 0; i < 8; i++) t += sh[i];
        stat[0] = t * (1.f / 512.f);
    }
    __syncthreads();
    const float m = stat[0];
    const float d0 = yl[0] - m, d1 = yl[1] - m;
    v = warpSum(d0 * d0 + d1 * d1);
    __syncthreads();   // pass-1 sh fully consumed before overwrite
    if (lane == 0) sh[wid] = v;
    __syncthreads();
    if (tid == 0) {
        float t = 0.f;
#pragma unroll
        for (int i = 0; i < 8; i++) t += sh[i];
        stat[1] = t * (1.f / 511.f);   // unbiased (ddof=1)
    }
    __syncthreads();
    const float sd  = sqrtf(stat[1]);
    const float inv = 1.f / (sd + EPSV);   // annotated-transformer: std + eps

    const size_t base = (size_t)token * DIM;
#pragma unroll
    for (int e = 0; e < 2; e++) {
        const int d = tid + e * 256;
        g_y[dir][base + d] = yl[e];
        g_z[dir][base + d] = gamma[d] * (yl[e] - m) * inv + beta[d];
    }
}

// ---------------- kernel 2/3: 3xTF32 GEMM, fused epilogues ----------------
// C[M=16384, N=512] = A[M,512] @ W[512,512] (+bias, +relu or +residual)
// Block tile 128x64, BK=32. 256 threads = 8 warps (4 m x 2 n), warp tile 32x32.
// MODE 0: g_h = relu(g_z @ W1 + b1)
// MODE 1: x_new = g_y + g_h @ W2 + b2 -> g_x and harness output slice.
template <int MODE>
__global__ void __launch_bounds__(256, 2)
gemm_tf32_kernel(const float* __restrict__ Wf, const float* __restrict__ Wb,
                 const float* __restrict__ biasF, const float* __restrict__ biasB,
                 float* __restrict__ out /* layer-offset base, MODE==1 */) {
    const int dir = blockIdx.z;
    const float* A    = (MODE == 0) ? g_z[dir] : g_h[dir];
    const float* Wm   = dir ? Wb : Wf;
    const float* bias = dir ? biasB : biasF;

    __shared__ float sA[128][36];
    __shared__ float sB[32][68];

    const int tid  = threadIdx.x;
    const int m0   = blockIdx.y * 128;
    const int n0   = blockIdx.x * 64;
    const int warp = tid >> 5, lane = tid & 31;
    const int wm = warp & 3;        // 0..3 -> m offset
    const int wn = warp >> 2;       // 0..1 -> n offset
    const int gid = lane >> 2;      // 0..7
    const int tig = lane & 3;       // 0..3

    float acc[2][4][4];
#pragma unroll
    for (int a = 0; a < 2; a++)
#pragma unroll
        for (int b = 0; b < 4; b++)
#pragma unroll
            for (int c = 0; c < 4; c++) acc[a][b][c] = 0.f;

    for (int kk = 0; kk < 512; kk += 32) {
        // --- load A tile 128x32 (float4, fully coalesced) ---
#pragma unroll
        for (int it = 0; it < 4; it++) {
            const int r = (tid >> 3) + it * 32;
            const int c = (tid & 7) * 4;
            const float4 vA = *(const float4*)(A + (size_t)(m0 + r) * 512 + kk + c);
            sA[r][c] = vA.x; sA[r][c + 1] = vA.y; sA[r][c + 2] = vA.z; sA[r][c + 3] = vA.w;
        }
        // --- load B tile 32x64 ---
#pragma unroll
        for (int it = 0; it < 2; it++) {
            const int r = (tid >> 4) + it * 16;
            const int c = (tid & 15) * 4;
            const float4 vB = *(const float4*)(Wm + (size_t)(kk + r) * 512 + n0 + c);
            sB[r][c] = vB.x; sB[r][c + 1] = vB.y; sB[r][c + 2] = vB.z; sB[r][c + 3] = vB.w;
        }
        __syncthreads();

#pragma unroll
        for (int k8 = 0; k8 < 4; k8++) {
            const int kb = k8 * 8;
            uint32_t ahi[2][4], alo[2][4];
#pragma unroll
            for (int mt = 0; mt < 2; mt++) {
                const int mr = wm * 32 + mt * 16 + gid;
                const int kc = kb + tig;
                split_tf32(sA[mr][kc],      ahi[mt][0], alo[mt][0]);
                split_tf32(sA[mr + 8][kc],  ahi[mt][1], alo[mt][1]);
                split_tf32(sA[mr][kc + 4],  ahi[mt][2], alo[mt][2]);
                split_tf32(sA[mr + 8][kc + 4], ahi[mt][3], alo[mt][3]);
            }
            uint32_t bhi[4][2], blo[4][2];
#pragma unroll
            for (int nt = 0; nt < 4; nt++) {
                const int nc = wn * 32 + nt * 8 + gid;
                const int kr = kb + tig;
                split_tf32(sB[kr][nc],     bhi[nt][0], blo[nt][0]);
                split_tf32(sB[kr + 4][nc], bhi[nt][1], blo[nt][1]);
            }
#pragma unroll
            for (int mt = 0; mt < 2; mt++)
#pragma unroll
                for (int nt = 0; nt < 4; nt++) {
                    mma_tf32(acc[mt][nt], ahi[mt], bhi[nt]);  // hi*hi
                    mma_tf32(acc[mt][nt], ahi[mt], blo[nt]);  // hi*lo
                    mma_tf32(acc[mt][nt], alo[mt], bhi[nt]);  // lo*hi
                }
        }
        __syncthreads();
    }

    // --- epilogue ---
#pragma unroll
    for (int mt = 0; mt < 2; mt++) {
#pragma unroll
        for (int nt = 0; nt < 4; nt++) {
            const int row = m0 + wm * 32 + mt * 16 + gid;
            const int col = n0 + wn * 32 + nt * 8 + tig * 2;
#pragma unroll
            for (int half = 0; half < 2; half++) {      // half 0: rows r, 1: r+8
                const int r = row + half * 8;
                const float c0 = acc[mt][nt][half * 2 + 0];
                const float c1 = acc[mt][nt][half * 2 + 1];
                if (MODE == 0) {
                    g_h[dir][(size_t)r * 512 + col]     = fmaxf(c0 + bias[col], 0.f);
                    g_h[dir][(size_t)r * 512 + col + 1] = fmaxf(c1 + bias[col + 1], 0.f);
                } else {
                    const size_t gi = (size_t)r * 512 + col;
                    const float v0 = c0 + bias[col]     + g_y[dir][gi];
                    const float v1 = c1 + bias[col + 1] + g_y[dir][gi + 1];
                    g_x[dir][gi]     = v0;
                    g_x[dir][gi + 1] = v1;
                    // out[layer][b][s][dir*512 + col], layer offset applied by host
                    const size_t oi = (size_t)r * 1024 + dir * 512 + col;
                    out[oi]     = v0;
                    out[oi + 1] = v1;
                }
            }
        }
    }
}

// ---------------- launcher ----------------
extern "C" void kernel_launch(void* const* d_in, const int* in_sizes, int n_in,
                              void* d_out, int out_size) {
    (void)in_sizes; (void)n_in; (void)out_size;
    const float* x        = (const float*)d_in[0];
    const float* fwd_pad  = (const float*)d_in[1];
    const float* bwd_pad  = (const float*)d_in[2];
    const float* fwd_w    = (const float*)d_in[3];
    const float* bwd_w    = (const float*)d_in[4];
    const float* fwd_w1   = (const float*)d_in[5];
    const float* fwd_b1   = (const float*)d_in[6];
    const float* fwd_w2   = (const float*)d_in[7];
    const float* fwd_b2   = (const float*)d_in[8];
    const float* fwd_g    = (const float*)d_in[9];
    const float* fwd_beta = (const float*)d_in[10];
    const float* bwd_w1   = (const float*)d_in[11];
    const float* bwd_b1   = (const float*)d_in[12];
    const float* bwd_w2   = (const float*)d_in[13];
    const float* bwd_b2   = (const float*)d_in[14];
    const float* bwd_g    = (const float*)d_in[15];
    const float* bwd_beta = (const float*)d_in[16];
    float* out = (float*)d_out;

    const dim3 gConv(MTOT, 2);
    const dim3 gGemm(DIM / 64, MTOT / 128, 2);   // (8, 128, 2)

    for (int i = 0; i < LNUM; i++) {
        conv_ln_kernel<<<gConv, 256>>>(
            x, i,
            fwd_pad + (size_t)i * WPAD * DIM, bwd_pad + (size_t)i * WPAD * DIM,
            fwd_w + i * (WPAD + 1), bwd_w + i * (WPAD + 1),
            fwd_g + i * DIM, fwd_beta + i * DIM,
            bwd_g + i * DIM, bwd_beta + i * DIM);

        gemm_tf32_kernel<0><<<gGemm, 256>>>(
            fwd_w1 + (size_t)i * DD, bwd_w1 + (size_t)i * DD,
            fwd_b1 + i * DIM, bwd_b1 + i * DIM, nullptr);

        gemm_tf32_kernel<1><<<gGemm, 256>>>(
            fwd_w2 + (size_t)i * DD, bwd_w2 + (size_t)i * DD,
            fwd_b2 + i * DIM, bwd_b2 + i * DIM,
            out + (size_t)i * MTOT * 1024);
    }
}

// round 3
// speedup vs baseline: 1.0705x; 1.0705x over previous
#include <cuda_runtime.h>
#include <cstdint>

#define LNUM 3
#define BSZ  32
#define SEQ  512
#define DIM  512
#define WPAD 3
#define MTOT (BSZ * SEQ)          // 16384 tokens
#define DD   (DIM * DIM)
#define EPSV 1e-6f

// GEMM tile config
#define BM 128
#define BN 64
#define BK 16
#define PA 20                      // sA pitch in uint2 (conflict-free frag reads)
#define PB 68                      // sB pitch in uint2
#define ASZ (BM * PA)              // 2560 uint2
#define BSZ2 (BK * PB)             // 1088 uint2
#define STG (ASZ + BSZ2)           // 3648 uint2 per stage
#define SMEM_BYTES (2 * STG * 8)   // 58368 B

// ---------------- scratch (device globals; no allocation) ----------------
__device__ float g_x[2][MTOT * DIM];        // carried state per direction (f32)
__device__ float g_y[2][MTOT * DIM];        // pre-LN conv output (residual, f32)
__device__ uint2 g_z[2][MTOT * DIM];        // LN output, split (hi,lo) tf32
__device__ uint2 g_h[2][MTOT * DIM];        // FFN hidden, split (hi,lo) tf32
__device__ uint2 g_w1s[2][LNUM * DD];       // split weights W1 (fwd/bwd)
__device__ uint2 g_w2s[2][LNUM * DD];       // split weights W2

// ---------------- helpers ----------------
__device__ __forceinline__ float warpSum(float v) {
#pragma unroll
    for (int o = 16; o > 0; o >>= 1) v += __shfl_xor_sync(0xffffffffu, v, o);
    return v;
}

__device__ __forceinline__ uint2 split_tf32(float x) {
    uint32_t h, l;
    asm("cvt.rna.tf32.f32 %0, %1;" : "=r"(h) : "f"(x));
    float rest = x - __uint_as_float(h);
    asm("cvt.rna.tf32.f32 %0, %1;" : "=r"(l) : "f"(rest));
    return make_uint2(h, l);
}

__device__ __forceinline__ void mma_tf32(float* c, const uint32_t* a, const uint32_t* b) {
    asm volatile(
        "mma.sync.aligned.m16n8k8.row.col.f32.tf32.tf32.f32 "
        "{%0,%1,%2,%3}, {%4,%5,%6,%7}, {%8,%9}, {%0,%1,%2,%3};"
        : "+f"(c[0]), "+f"(c[1]), "+f"(c[2]), "+f"(c[3])
        : "r"(a[0]), "r"(a[1]), "r"(a[2]), "r"(a[3]), "r"(b[0]), "r"(b[1]));
}

__device__ __forceinline__ void cpa16(uint32_t s, const uint2* g) {
    size_t ga;
    asm("cvta.to.global.u64 %0, %1;" : "=l"(ga) : "l"(g));
    asm volatile("cp.async.cg.shared.global [%0], [%1], 16;\n" :: "r"(s), "l"(ga));
}
__device__ __forceinline__ void cpa_commit() { asm volatile("cp.async.commit_group;\n"); }
template <int N> __device__ __forceinline__ void cpa_wait() {
    asm volatile("cp.async.wait_group %0;\n" :: "n"(N));
}

// ---------------- kernel 0: split weights into (hi,lo) tf32 ----------------
// Handles 4 tensors (fwd_w1, bwd_w1, fwd_w2, bwd_w2), each L*DD floats.
__global__ void split_weights_kernel(const float* __restrict__ fw1,
                                     const float* __restrict__ bw1,
                                     const float* __restrict__ fw2,
                                     const float* __restrict__ bw2) {
    const int PER = LNUM * DD / 4;                    // float4 count per tensor
    int idx = blockIdx.x * blockDim.x + threadIdx.x;  // global float4 id
    const int t = idx / PER;
    const int r = idx - t * PER;
    const float* src = (t == 0) ? fw1 : (t == 1) ? bw1 : (t == 2) ? fw2 : bw2;
    uint2* dst = (t == 0) ? g_w1s[0] : (t == 1) ? g_w1s[1] : (t == 2) ? g_w2s[0] : g_w2s[1];
    const float4 v = *(const float4*)(src + (size_t)r * 4);
    uint2* d = dst + (size_t)r * 4;
    uint2 s0 = split_tf32(v.x), s1 = split_tf32(v.y), s2 = split_tf32(v.z), s3 = split_tf32(v.w);
    *(uint4*)(d)     = make_uint4(s0.x, s0.y, s1.x, s1.y);
    *(uint4*)(d + 2) = make_uint4(s2.x, s2.y, s3.x, s3.y);
}

// ---------------- kernel 1: window conv + LayerNorm, warp-per-token ----------------
// grid: (MTOT/8, 2), block 256 = 8 warps = 8 tokens. Pure warp reductions.
__global__ void conv_ln_kernel(const float* __restrict__ ext_x, int layer,
                               const float* __restrict__ fpad,
                               const float* __restrict__ bpad,
                               const float* __restrict__ fwt,
                               const float* __restrict__ bwt,
                               const float* __restrict__ fg, const float* __restrict__ fb,
                               const float* __restrict__ bg, const float* __restrict__ bb) {
    const int dir  = blockIdx.y;
    const int tid  = threadIdx.x;
    const int lane = tid & 31;
    const int token = blockIdx.x * 8 + (tid >> 5);
    const int b = token >> 9;
    const int s = token & 511;
    const float* src   = (layer == 0) ? ext_x : g_x[dir];
    const float* wt    = dir ? bwt : fwt;
    const float* gamma = dir ? bg : fg;
    const float* beta  = dir ? bb : fb;
    const int off = dir ? WPAD : 0;

    float w[4];
#pragma unroll
    for (int k = 0; k < 4; k++) w[k] = wt[k];

    float4 acc[4];
#pragma unroll
    for (int c = 0; c < 4; c++) acc[c] = make_float4(0.f, 0.f, 0.f, 0.f);

#pragma unroll
    for (int k = 0; k < 4; k++) {
        const int j = s + off + k;
        const float* rowp;
        if (j < WPAD)                rowp = fpad + (size_t)j * DIM;
        else if (j < WPAD + SEQ)     rowp = src + ((size_t)b * SEQ + (j - WPAD)) * DIM;
        else                         rowp = bpad + (size_t)(j - WPAD - SEQ) * DIM;
        const float wk = w[k];
#pragma unroll
        for (int c = 0; c < 4; c++) {
            const float4 v = *(const float4*)(rowp + lane * 4 + c * 128);
            acc[c].x += wk * v.x; acc[c].y += wk * v.y;
            acc[c].z += wk * v.z; acc[c].w += wk * v.w;
        }
    }

    float lsum = 0.f;
#pragma unroll
    for (int c = 0; c < 4; c++) lsum += acc[c].x + acc[c].y + acc[c].z + acc[c].w;
    const float m = warpSum(lsum) * (1.f / 512.f);

    float lvar = 0.f;
#pragma unroll
    for (int c = 0; c < 4; c++) {
        const float dx = acc[c].x - m, dy = acc[c].y - m, dz = acc[c].z - m, dw = acc[c].w - m;
        lvar += dx * dx + dy * dy + dz * dz + dw * dw;
    }
    const float var = warpSum(lvar) * (1.f / 511.f);     // ddof=1
    const float inv = 1.f / (sqrtf(var) + EPSV);          // std + eps

    float* yout = g_y[dir] + (size_t)token * DIM;
    uint2* zout = g_z[dir] + (size_t)token * DIM;
#pragma unroll
    for (int c = 0; c < 4; c++) {
        const int col = lane * 4 + c * 128;
        *(float4*)(yout + col) = acc[c];
        const float4 gm = *(const float4*)(gamma + col);
        const float4 bt = *(const float4*)(beta + col);
        float4 z;
        z.x = gm.x * (acc[c].x - m) * inv + bt.x;
        z.y = gm.y * (acc[c].y - m) * inv + bt.y;
        z.z = gm.z * (acc[c].z - m) * inv + bt.z;
        z.w = gm.w * (acc[c].w - m) * inv + bt.w;
        const uint2 s0 = split_tf32(z.x), s1 = split_tf32(z.y),
                    s2 = split_tf32(z.z), s3 = split_tf32(z.w);
        *(uint4*)(zout + col)     = make_uint4(s0.x, s0.y, s1.x, s1.y);
        *(uint4*)(zout + col + 2) = make_uint4(s2.x, s2.y, s3.x, s3.y);
    }
}

// ---------------- GEMM: pure-MMA inner loop, cp.async 2-stage pipeline ----------------
// C[M,512] = A[M,512] @ W[512,512]; 3xTF32 with pre-split (hi,lo) operands.
// MODE 0: g_h = split(relu(g_z @ W1 + b1))
// MODE 1: xnew = g_y + g_h @ W2 + b2 -> g_x and harness output.
template <int MODE>
__global__ void __launch_bounds__(256, 2)
gemm_tf32_kernel(int layer,
                 const float* __restrict__ biasF, const float* __restrict__ biasB,
                 float* __restrict__ out) {
    extern __shared__ uint2 smem[];
    const int dir = blockIdx.z;
    const uint2* A    = (MODE == 0) ? g_z[dir] : g_h[dir];
    const uint2* Wm   = ((MODE == 0) ? g_w1s[dir] : g_w2s[dir]) + (size_t)layer * DD;
    const float* bias = dir ? biasB : biasF;

    const int tid  = threadIdx.x;
    const int m0   = blockIdx.y * BM;
    const int n0   = blockIdx.x * BN;
    const int warp = tid >> 5, lane = tid & 31;
    const int wm = warp & 3;
    const int wn = warp >> 2;
    const int gid = lane >> 2;
    const int tig = lane & 3;

    const uint32_t sbase = (uint32_t)__cvta_generic_to_shared(smem);

    float acc[2][4][4];
#pragma unroll
    for (int a = 0; a < 2; a++)
#pragma unroll
        for (int b = 0; b < 4; b++)
#pragma unroll
            for (int c = 0; c < 4; c++) acc[a][b][c] = 0.f;

    // issue one stage's cp.async loads
    auto issue = [&](int stage, int kk) {
        const uint32_t as = sbase + stage * (STG * 8);
        const uint32_t bs = as + ASZ * 8;
        // A: 128 rows x 16 uint2 -> 1024 chunks of 16B, 4 per thread
#pragma unroll
        for (int i = 0; i < 4; i++) {
            const int c = tid + i * 256;
            const int row = c >> 3;
            const int col = (c & 7) * 2;
            cpa16(as + (row * PA + col) * 8, A + (size_t)(m0 + row) * 512 + kk + col);
        }
        // B: 16 rows x 64 uint2 -> 512 chunks of 16B, 2 per thread
#pragma unroll
        for (int i = 0; i < 2; i++) {
            const int c = tid + i * 256;
            const int row = c >> 5;
            const int col = (c & 31) * 2;
            cpa16(bs + (row * PB + col) * 8, Wm + (size_t)(kk + row) * 512 + n0 + col);
        }
        cpa_commit();
    };

    issue(0, 0);

    const int NT = 512 / BK;     // 32
    for (int kt = 0; kt < NT; kt++) {
        const int cur = kt & 1;
        if (kt + 1 < NT) {
            issue(cur ^ 1, (kt + 1) * BK);
            cpa_wait<1>();
        } else {
            cpa_wait<0>();
        }
        __syncthreads();

        const uint2* sA = smem + cur * STG;
        const uint2* sB = smem + cur * STG + ASZ;

#pragma unroll
        for (int k8 = 0; k8 < 2; k8++) {
            const int kb = k8 * 8;
            uint32_t ahi[2][4], alo[2][4];
#pragma unroll
            for (int mt = 0; mt < 2; mt++) {
                const int mr = wm * 32 + mt * 16 + gid;
                const int kc = kb + tig;
                const uint2 a0 = sA[mr * PA + kc];
                const uint2 a1 = sA[(mr + 8) * PA + kc];
                const uint2 a2 = sA[mr * PA + kc + 4];
                const uint2 a3 = sA[(mr + 8) * PA + kc + 4];
                ahi[mt][0] = a0.x; alo[mt][0] = a0.y;
                ahi[mt][1] = a1.x; alo[mt][1] = a1.y;
                ahi[mt][2] = a2.x; alo[mt][2] = a2.y;
                ahi[mt][3] = a3.x; alo[mt][3] = a3.y;
            }
            uint32_t bhi[4][2], blo[4][2];
#pragma unroll
            for (int nt = 0; nt < 4; nt++) {
                const int nc = wn * 32 + nt * 8 + gid;
                const int kr = kb + tig;
                const uint2 b0 = sB[kr * PB + nc];
                const uint2 b1 = sB[(kr + 4) * PB + nc];
                bhi[nt][0] = b0.x; blo[nt][0] = b0.y;
                bhi[nt][1] = b1.x; blo[nt][1] = b1.y;
            }
#pragma unroll
            for (int mt = 0; mt < 2; mt++)
#pragma unroll
                for (int nt = 0; nt < 4; nt++) {
                    mma_tf32(acc[mt][nt], ahi[mt], bhi[nt]);
                    mma_tf32(acc[mt][nt], ahi[mt], blo[nt]);
                    mma_tf32(acc[mt][nt], alo[mt], bhi[nt]);
                }
        }
        __syncthreads();
    }

    // --- epilogue ---
#pragma unroll
    for (int mt = 0; mt < 2; mt++) {
#pragma unroll
        for (int nt = 0; nt < 4; nt++) {
            const int row = m0 + wm * 32 + mt * 16 + gid;
            const int col = n0 + wn * 32 + nt * 8 + tig * 2;
#pragma unroll
            for (int half = 0; half < 2; half++) {
                const int r = row + half * 8;
                const float c0 = acc[mt][nt][half * 2 + 0];
                const float c1 = acc[mt][nt][half * 2 + 1];
                if (MODE == 0) {
                    const float v0 = fmaxf(c0 + bias[col], 0.f);
                    const float v1 = fmaxf(c1 + bias[col + 1], 0.f);
                    const uint2 s0 = split_tf32(v0), s1 = split_tf32(v1);
                    *(uint4*)(g_h[dir] + (size_t)r * 512 + col) =
                        make_uint4(s0.x, s0.y, s1.x, s1.y);
                } else {
                    const size_t gi = (size_t)r * 512 + col;
                    const float2 yv = *(const float2*)(g_y[dir] + gi);
                    const float v0 = c0 + bias[col]     + yv.x;
                    const float v1 = c1 + bias[col + 1] + yv.y;
                    *(float2*)(g_x[dir] + gi) = make_float2(v0, v1);
                    const size_t oi = (size_t)r * 1024 + dir * 512 + col;
                    *(float2*)(out + oi) = make_float2(v0, v1);
                }
            }
        }
    }
}

// ---------------- launcher ----------------
extern "C" void kernel_launch(void* const* d_in, const int* in_sizes, int n_in,
                              void* d_out, int out_size) {
    (void)in_sizes; (void)n_in; (void)out_size;
    const float* x        = (const float*)d_in[0];
    const float* fwd_pad  = (const float*)d_in[1];
    const float* bwd_pad  = (const float*)d_in[2];
    const float* fwd_w    = (const float*)d_in[3];
    const float* bwd_w    = (const float*)d_in[4];
    const float* fwd_w1   = (const float*)d_in[5];
    const float* fwd_b1   = (const float*)d_in[6];
    const float* fwd_w2   = (const float*)d_in[7];
    const float* fwd_b2   = (const float*)d_in[8];
    const float* fwd_g    = (const float*)d_in[9];
    const float* fwd_beta = (const float*)d_in[10];
    const float* bwd_w1   = (const float*)d_in[11];
    const float* bwd_b1   = (const float*)d_in[12];
    const float* bwd_w2   = (const float*)d_in[13];
    const float* bwd_b2   = (const float*)d_in[14];
    const float* bwd_g    = (const float*)d_in[15];
    const float* bwd_beta = (const float*)d_in[16];
    float* out = (float*)d_out;

    static bool attr_done = false;
    if (!attr_done) {
        cudaFuncSetAttribute(gemm_tf32_kernel<0>,
                             cudaFuncAttributeMaxDynamicSharedMemorySize, SMEM_BYTES);
        cudaFuncSetAttribute(gemm_tf32_kernel<1>,
                             cudaFuncAttributeMaxDynamicSharedMemorySize, SMEM_BYTES);
        attr_done = true;
    }

    // split all weights (4 tensors x L*DD floats, as float4s)
    {
        const int total4 = 4 * LNUM * DD / 4;
        split_weights_kernel<<<total4 / 256, 256>>>(fwd_w1, bwd_w1, fwd_w2, bwd_w2);
    }

    const dim3 gConv(MTOT / 8, 2);
    const dim3 gGemm(DIM / BN, MTOT / BM, 2);   // (8, 128, 2)

    for (int i = 0; i < LNUM; i++) {
        conv_ln_kernel<<<gConv, 256>>>(
            x, i,
            fwd_pad + (size_t)i * WPAD * DIM, bwd_pad + (size_t)i * WPAD * DIM,
            fwd_w + i * (WPAD + 1), bwd_w + i * (WPAD + 1),
            fwd_g + i * DIM, fwd_beta + i * DIM,
            bwd_g + i * DIM, bwd_beta + i * DIM);

        gemm_tf32_kernel<0><<<gGemm, 256, SMEM_BYTES>>>(
            i, fwd_b1 + i * DIM, bwd_b1 + i * DIM, nullptr);

        gemm_tf32_kernel<1><<<gGemm, 256, SMEM_BYTES>>>(
            i, fwd_b2 + i * DIM, bwd_b2 + i * DIM,
            out + (size_t)i * MTOT * 1024);
    }
}